// round 6
// baseline (speedup 1.0000x reference)
#include <cuda_runtime.h>
#include <math.h>
#include <float.h>

// ---------------- problem constants (fixed by setup_inputs) ----------------
#define N0_   320000
#define N1_   80000
#define N2_   16000
#define E1_   800000
#define E2_   160000
#define INC_  128
#define F1_   256      // H1*HID = 4*64
#define F2_   48       // OUT_C
#define NEG_SLOPE 0.2f

// ---------------- scratch (static device globals; no allocs) ----------------
// g_xr1 doubles as h1 after edge pass 1 (xr1 dead once edge1 completes).
// g_agg1 doubles as xl2/xr2 after node1 (agg1 dead once node1 completes).
__device__ __align__(128) float g_xl1[(size_t)N0_ * F1_];   // 327 MB
__device__ __align__(128) float g_xr1[(size_t)N1_ * F1_];   // 82 MB (also h1)
__device__ __align__(128) float g_agg1[(size_t)N1_ * F1_];  // 82 MB (also xl2|xr2)
__device__ __align__(128) float g_den1[N1_ * 4];            // layout per node: [h0,h2,h1,h3]
__device__ __align__(128) float g_agg2[(size_t)N2_ * F2_];
__device__ __align__(128) float g_den2[N2_];

#define XL2_OFF 0
#define XR2_OFF ((size_t)N1_ * F2_)

__device__ __forceinline__ float lrelu(float v) { return v > 0.f ? v : NEG_SLOPE * v; }

// packed f32x2 helpers (Blackwell FFMA2 pipe — ptxas never auto-fuses from C++)
__device__ __forceinline__ unsigned long long pk2(float a, float b) {
    unsigned long long r;
    asm("mov.b64 %0, {%1, %2};" : "=l"(r) : "f"(a), "f"(b));
    return r;
}
__device__ __forceinline__ void fma2(unsigned long long& d, unsigned long long a,
                                     unsigned long long b) {
    asm("fma.rn.f32x2 %0, %1, %2, %3;" : "=l"(d) : "l"(a), "l"(b), "l"(d));
}
__device__ __forceinline__ float2 unpk2(unsigned long long v) {
    float2 r;
    asm("mov.b64 {%0, %1}, %2;" : "=f"(r.x), "=f"(r.y) : "l"(v));
    return r;
}
// no-return global reductions (PTX ISA 8.1+ for v2/v4, sm_90+)
__device__ __forceinline__ void red_add_v4(float* p, float a, float b, float c, float d) {
    asm volatile("red.global.add.v4.f32 [%0], {%1, %2, %3, %4};"
                 :: "l"(p), "f"(a), "f"(b), "f"(c), "f"(d) : "memory");
}
__device__ __forceinline__ void red_add_v2(float* p, float a, float b) {
    asm volatile("red.global.add.v2.f32 [%0], {%1, %2};"
                 :: "l"(p), "f"(a), "f"(b) : "memory");
}
__device__ __forceinline__ void red_add_f32(float* p, float a) {
    asm volatile("red.global.add.f32 [%0], %1;"
                 :: "l"(p), "f"(a) : "memory");
}

// ---------------- zero init ----------------
__global__ void zero1_kernel() {
    int i = blockIdx.x * 256 + threadIdx.x;
    if (i < N1_ * F1_) g_agg1[i] = 0.f;
    if (i < N1_ * 4)   g_den1[i] = 0.f;
}
__global__ void zero2_kernel() {
    int i = blockIdx.x * 256 + threadIdx.x;
    if (i < N2_ * F2_) g_agg2[i] = 0.f;
    if (i < N2_)       g_den2[i] = 0.f;
}

// ---------------- SGEMM: C[M,N] = A[M,K] @ B[K,N] + bias ----------------
// BM=128, BN=64, BK=16, 256 threads, 8x4 micro-tile on packed f32x2 FMA.
// Register double-buffered k-loop: tile k+1 global loads issue before tile k compute.
// mode: 0 -> A=x,    C=g_xl1          ; 1 -> A=x,    C=g_xr1
//       2 -> A=g_xr1(h1), C=agg1[XL2] ; 3 -> A=g_xr1(h1), C=agg1[XR2]
// Requires M % 128 == 0, K % 16 == 0 (all hold).
__global__ __launch_bounds__(256)
void sgemm_bias(const float* __restrict__ Ain, const float* __restrict__ B,
                const float* __restrict__ bias, int mode, int M, int N, int K)
{
    const float* A = (mode >= 2) ? g_xr1 : Ain;
    float* C = (mode == 0) ? g_xl1 : (mode == 1) ? g_xr1
             : (mode == 2) ? (g_agg1 + XL2_OFF) : (g_agg1 + XR2_OFF);

    __shared__ float As[16][132];   // [k][m], padded
    __shared__ float Bs[16][68];    // [k][n], padded

    const int tid = threadIdx.x;
    const int tx = tid & 15;         // n micro index (4 cols)
    const int ty = tid >> 4;         // m micro index (8 rows)
    const int m0 = blockIdx.x * 128;
    const int n0 = blockIdx.y * 64;

    const int ar = tid >> 2;         // 0..63
    const int ak = (tid & 3) * 4;    // 0,4,8,12
    const int bk = tid >> 4;         // 0..15
    const int bn = (tid & 15) * 4;   // 0..60
    const bool bok = (n0 + bn + 3 < N);

    unsigned long long accp[8][2];
#pragma unroll
    for (int i = 0; i < 8; i++) { accp[i][0] = 0ull; accp[i][1] = 0ull; }

    // prologue: load tile 0 into registers
    float4 a0 = *(const float4*)&A[(size_t)(m0 + ar) * K + ak];
    float4 a1 = *(const float4*)&A[(size_t)(m0 + ar + 64) * K + ak];
    float4 b  = make_float4(0.f, 0.f, 0.f, 0.f);
    if (bok) b = *(const float4*)&B[(size_t)bk * N + n0 + bn];

    for (int k0 = 0; k0 < K; k0 += 16) {
        __syncthreads();   // previous tile's compute readers done
        As[ak + 0][ar] = a0.x; As[ak + 1][ar] = a0.y; As[ak + 2][ar] = a0.z; As[ak + 3][ar] = a0.w;
        As[ak + 0][ar + 64] = a1.x; As[ak + 1][ar + 64] = a1.y; As[ak + 2][ar + 64] = a1.z; As[ak + 3][ar + 64] = a1.w;
        *(float4*)&Bs[bk][bn] = b;
        __syncthreads();

        // prefetch next tile (issued before compute; latency hidden by FMA work)
        if (k0 + 16 < K) {
            a0 = *(const float4*)&A[(size_t)(m0 + ar) * K + k0 + 16 + ak];
            a1 = *(const float4*)&A[(size_t)(m0 + ar + 64) * K + k0 + 16 + ak];
            if (bok) b = *(const float4*)&B[(size_t)(k0 + 16 + bk) * N + n0 + bn];
        }

#pragma unroll
        for (int kk = 0; kk < 16; ++kk) {
            float4 af0 = *(const float4*)&As[kk][ty * 8];
            float4 af1 = *(const float4*)&As[kk][ty * 8 + 4];
            const unsigned long long* b64 =
                (const unsigned long long*)&Bs[kk][tx * 4];
            unsigned long long b01 = b64[0], b23 = b64[1];
            float am[8] = {af0.x, af0.y, af0.z, af0.w, af1.x, af1.y, af1.z, af1.w};
#pragma unroll
            for (int i = 0; i < 8; i++) {
                unsigned long long ap = pk2(am[i], am[i]);
                fma2(accp[i][0], ap, b01);
                fma2(accp[i][1], ap, b23);
            }
        }
    }

    const int ncol = n0 + tx * 4;
    if (ncol + 3 < N) {
        float4 bb = *(const float4*)&bias[ncol];
#pragma unroll
        for (int i = 0; i < 8; i++) {
            int r = m0 + ty * 8 + i;
            float2 p0 = unpk2(accp[i][0]);
            float2 p1 = unpk2(accp[i][1]);
            float4 o = make_float4(p0.x + bb.x, p0.y + bb.y, p1.x + bb.z, p1.y + bb.w);
            *(float4*)&C[(size_t)r * N + ncol] = o;
        }
    }
}

// ---------------- layer-1 edge pass: one warp per edge ----------------
// alpha_h = sum_c lrelu(xl[s,h,c]+xr[d,h,c])*att[h,c]; ex = exp(alpha)
// agg1[d,h,:] += ex * xl[s,h,:];  den1[d,(perm)h] += ex  (max-free softmax, deferred norm)
// den per-node layout is [h0,h2,h1,h3]: lane0 owns {h0,h2}, lane16 owns {h1,h3},
// so each writing lane issues one red.v2.
__global__ __launch_bounds__(256)
void edge1_kernel(const int* __restrict__ src, const int* __restrict__ dst,
                  const float* __restrict__ att)
{
    int w = (blockIdx.x * 256 + threadIdx.x) >> 5;
    if (w >= E1_) return;
    int lane = threadIdx.x & 31;
    int s = src[w], d = dst[w];

    const float4* xl4 = (const float4*)g_xl1 + (size_t)s * 64;
    const float4* xr4 = (const float4*)g_xr1 + (size_t)d * 64;
    const float4* at4 = (const float4*)att;

    float4 A0 = xl4[lane], A1 = xl4[lane + 32];
    float4 B0 = xr4[lane], B1 = xr4[lane + 32];
    float4 C0 = at4[lane], C1 = at4[lane + 32];

    float p0 = lrelu(A0.x + B0.x) * C0.x + lrelu(A0.y + B0.y) * C0.y
             + lrelu(A0.z + B0.z) * C0.z + lrelu(A0.w + B0.w) * C0.w;
    float p1 = lrelu(A1.x + B1.x) * C1.x + lrelu(A1.y + B1.y) * C1.y
             + lrelu(A1.z + B1.z) * C1.z + lrelu(A1.w + B1.w) * C1.w;

    // reduce within 16-lane halves: lanes 0-15 -> head 0 (p0) / 2 (p1); 16-31 -> 1 / 3
#pragma unroll
    for (int o = 8; o > 0; o >>= 1) {
        p0 += __shfl_xor_sync(0xffffffffu, p0, o);
        p1 += __shfl_xor_sync(0xffffffffu, p1, o);
    }
    float ex0 = __expf(p0);   // fast MUFU exp: rel err ~2^-21, << 1e-3 gate
    float ex1 = __expf(p1);

    if (lane == 0)  red_add_v2(&g_den1[d * 4 + 0], ex0, ex1);   // h0, h2
    if (lane == 16) red_add_v2(&g_den1[d * 4 + 2], ex0, ex1);   // h1, h3

    float* agg = g_agg1 + (size_t)d * 256;
    int j = lane * 4;
    red_add_v4(&agg[j],       A0.x * ex0, A0.y * ex0, A0.z * ex0, A0.w * ex0);
    red_add_v4(&agg[128 + j], A1.x * ex1, A1.y * ex1, A1.z * ex1, A1.w * ex1);
}

// ---------------- layer-1 node epilogue: h1 = relu(agg/den + bias1) -> g_xr1 ----------------
__global__ void node1_kernel(const float* __restrict__ bias1)
{
    int i = blockIdx.x * 256 + threadIdx.x;     // float4 index
    if (i >= N1_ * 64) return;
    int n = i >> 6, f = i & 63, h = f >> 4;
    int dh = ((h & 1) << 1) | (h >> 1);         // den permutation: h0->0,h1->2,h2->1,h3->3
    float inv = 1.f / (g_den1[n * 4 + dh] + 1e-16f);
    float4 v = ((const float4*)g_agg1)[i];
    float4 b = ((const float4*)bias1)[f];
    v.x = fmaxf(v.x * inv + b.x, 0.f);
    v.y = fmaxf(v.y * inv + b.y, 0.f);
    v.z = fmaxf(v.z * inv + b.z, 0.f);
    v.w = fmaxf(v.w * inv + b.w, 0.f);
    ((float4*)g_xr1)[i] = v;   // h1 aliases xr1 (xr1 dead after edge1)
}

// ---------------- layer-2 edge pass: one warp per edge, 1 head, 48 ch ----------------
__global__ __launch_bounds__(256)
void edge2_kernel(const int* __restrict__ src, const int* __restrict__ dst,
                  const float* __restrict__ att)
{
    int w = (blockIdx.x * 256 + threadIdx.x) >> 5;
    if (w >= E2_) return;
    int lane = threadIdx.x & 31;
    int s = src[w], d = dst[w];

    const float4* xl2 = (const float4*)(g_agg1 + XL2_OFF);
    const float4* xr2 = (const float4*)(g_agg1 + XR2_OFF);

    float4 A = make_float4(0.f, 0.f, 0.f, 0.f), B = A, C = A;
    if (lane < 12) {
        A = xl2[(size_t)s * 12 + lane];
        B = xr2[(size_t)d * 12 + lane];
        C = ((const float4*)att)[lane];
    }
    float p = lrelu(A.x + B.x) * C.x + lrelu(A.y + B.y) * C.y
            + lrelu(A.z + B.z) * C.z + lrelu(A.w + B.w) * C.w;
#pragma unroll
    for (int o = 16; o > 0; o >>= 1) p += __shfl_xor_sync(0xffffffffu, p, o);
    float ex = __expf(p);
    if (lane == 0) red_add_f32(&g_den2[d], ex);
    if (lane < 12) {
        float* agg = g_agg2 + (size_t)d * 48 + lane * 4;
        red_add_v4(agg, A.x * ex, A.y * ex, A.z * ex, A.w * ex);
    }
}

// ---------------- layer-2 node epilogue + log_softmax: one warp per node ----------------
__global__ void node2_kernel(const float* __restrict__ bias2, float* __restrict__ out)
{
    int w = (blockIdx.x * 256 + threadIdx.x) >> 5;
    if (w >= N2_) return;
    int lane = threadIdx.x & 31;
    float inv = 1.f / (g_den2[w] + 1e-16f);

    float4 v = make_float4(0.f, 0.f, 0.f, 0.f);
    if (lane < 12) {
        v = ((const float4*)g_agg2)[(size_t)w * 12 + lane];
        float4 b = ((const float4*)bias2)[lane];
        v.x = v.x * inv + b.x;
        v.y = v.y * inv + b.y;
        v.z = v.z * inv + b.z;
        v.w = v.w * inv + b.w;
    }
    float mx = (lane < 12) ? fmaxf(fmaxf(v.x, v.y), fmaxf(v.z, v.w)) : -FLT_MAX;
#pragma unroll
    for (int o = 16; o > 0; o >>= 1) mx = fmaxf(mx, __shfl_xor_sync(0xffffffffu, mx, o));
    float se = (lane < 12)
             ? (__expf(v.x - mx) + __expf(v.y - mx) + __expf(v.z - mx) + __expf(v.w - mx)) : 0.f;
#pragma unroll
    for (int o = 16; o > 0; o >>= 1) se += __shfl_xor_sync(0xffffffffu, se, o);
    float lse = logf(se);
    if (lane < 12) {
        float4 o4 = make_float4(v.x - mx - lse, v.y - mx - lse,
                                v.z - mx - lse, v.w - mx - lse);
        ((float4*)out)[(size_t)w * 12 + lane] = o4;
    }
}

// ---------------- launch ----------------
extern "C" void kernel_launch(void* const* d_in, const int* in_sizes, int n_in,
                              void* d_out, int out_size)
{
    const float* x     = (const float*)d_in[0];
    const float* Wl1   = (const float*)d_in[1];
    const float* bl1   = (const float*)d_in[2];
    const float* Wr1   = (const float*)d_in[3];
    const float* br1   = (const float*)d_in[4];
    const float* att1  = (const float*)d_in[5];
    const float* bias1 = (const float*)d_in[6];
    const float* Wl2   = (const float*)d_in[7];
    const float* bl2   = (const float*)d_in[8];
    const float* Wr2   = (const float*)d_in[9];
    const float* br2   = (const float*)d_in[10];
    const float* att2  = (const float*)d_in[11];
    const float* bias2 = (const float*)d_in[12];
    const int* src1 = (const int*)d_in[13];
    const int* dst1 = (const int*)d_in[14];
    const int* src2 = (const int*)d_in[15];
    const int* dst2 = (const int*)d_in[16];
    float* out = (float*)d_out;

    // zero accumulators
    zero1_kernel<<<(N1_ * F1_ + 255) / 256, 256>>>();
    zero2_kernel<<<(N2_ * F2_ + 255) / 256, 256>>>();

    // layer-1 transforms
    sgemm_bias<<<dim3(N0_ / 128, F1_ / 64), 256>>>(x, Wl1, bl1, 0, N0_, F1_, INC_);
    sgemm_bias<<<dim3(N1_ / 128, F1_ / 64), 256>>>(x, Wr1, br1, 1, N1_, F1_, INC_);

    // layer-1 edge aggregation + node epilogue
    edge1_kernel<<<(E1_ * 32 + 255) / 256, 256>>>(src1, dst1, att1);
    node1_kernel<<<(N1_ * 64 + 255) / 256, 256>>>(bias1);

    // layer-2 transforms (A = h1 in g_xr1, selected by mode)
    sgemm_bias<<<dim3(N1_ / 128, 1), 256>>>(x, Wl2, bl2, 2, N1_, F2_, F1_);
    sgemm_bias<<<dim3(N2_ / 128, 1), 256>>>(x, Wr2, br2, 3, N2_, F2_, F1_);

    // layer-2 edge aggregation + log_softmax epilogue
    edge2_kernel<<<(E2_ * 32 + 255) / 256, 256>>>(src2, dst2, att2);
    node2_kernel<<<(N2_ * 32 + 255) / 256, 256>>>(bias2, out);
}